// round 10
// baseline (speedup 1.0000x reference)
#include <cuda_runtime.h>
#include <cuda_fp16.h>
#include <cstdint>

#define NWARPS    4
#define NTHREADS  (NWARPS * 32)
#define TM        (NWARPS * 16)     // 64 rows per CTA

// Packed fp16 hi/lo B-fragments. Per (layer,kt16,nt8,lane): uint4 =
// {bh0(k=2t,2t+1), bh1(k=2t+8,2t+9), bl0, bl1} for col n0+g. 16384 uint4 = 256KB.
__device__ uint4 g_wpk[16384];

// layer tables (pack kernel): NT=N/8, block cumsum, uint4 offset
__constant__ int c_NT[9]   = {8,8,8,10,10,10,18,8,8};
__constant__ int c_bcum[10]= {0,32,64,96,146,196,246,408,480,512};
__constant__ int c_u4off[9]= {0,1024,2048,3072,4672,6272,7872,13056,15360};

// Epilogue segment descriptors (31 segments of 8 after the 64 hb outputs)
__constant__ int c_kind[31] = {3,0,2,2,2,2,2,0,0,0,0,0,6,6,6,6,0,1,5,6,1,0,5,4,0,6,6,6,6,6,6};
__constant__ int c_col[31]  = {18,20,22,23,24,25,26,27,28,29,30,31,0,1,2,3,35,36,37,4,32,33,34,19,38,5,6,7,8,9,10};
__constant__ int c_scol[11] = {40,41,42,43,39,44,45,46,47,48,49};
__constant__ int c_widx[11] = {0,2,3,5,1,4,4,4,4,4,4};

struct Params {
    const float *state;
    const float *suit, *rank;
    const float *hW1,*hb1,*hW2,*hb2,*hW3,*hb3;
    const float *bW1,*bb1,*bW2,*bb2,*bW3,*bb3;
    const float *cW1,*cb1,*cW2,*cb2,*cW3,*cb3;
    const float *pos,*action,*active,*street,*nump,*blind;
    const float *sW,*sb;
    float *out;
    int nrows;
};

__device__ __forceinline__ float leaky(float v) { return v > 0.0f ? v : 0.01f * v; }

__device__ __forceinline__ uint32_t h2bits(__half2 h) {
    return *reinterpret_cast<uint32_t*>(&h);
}

// split (x,y) into packed fp16 hi and lo half2 bit patterns
__device__ __forceinline__ void split2(float x, float y, uint32_t& hi, uint32_t& lo) {
    __half2 h = __floats2half2_rn(x, y);
    float2 hf = __half22float2(h);
    __half2 l = __floats2half2_rn(x - hf.x, y - hf.y);
    hi = h2bits(h);
    lo = h2bits(l);
}

__device__ __forceinline__ void mma16(float (&c)[4],
                                      uint32_t a0, uint32_t a1, uint32_t a2, uint32_t a3,
                                      uint32_t b0, uint32_t b1)
{
    asm volatile("mma.sync.aligned.m16n8k16.row.col.f32.f16.f16.f32 "
                 "{%0,%1,%2,%3}, {%4,%5,%6,%7}, {%8,%9}, {%0,%1,%2,%3};\n"
                 : "+f"(c[0]), "+f"(c[1]), "+f"(c[2]), "+f"(c[3])
                 : "r"(a0), "r"(a1), "r"(a2), "r"(a3), "r"(b0), "r"(b1));
}

// ---------------- per-lane smem frag ring ----------------
// Per warp: 9 kt slots x 8 words (a0..a3 hi, a0..a3 lo), stored as pairs:
// pair q (= kt*4 + {0:(a0,a1)h,1:(a2,a3)h,2:lo,3:lo}) at word offset q*64 + lane*2.
// All traffic is lane-private: STS.64/LDS.64, conflict-free, no syncs needed.
#define SB_WARP_WORDS 2304    // 9*4*64

__device__ __forceinline__ void sb_emit(uint32_t* sb, int j, int odd,
                                        float v0, float v1, float v2, float v3)
{
    uint32_t h0, l0, h1, l1;
    split2(v0, v1, h0, l0);
    split2(v2, v3, h1, l1);
    *(uint2*)(sb + (j * 4 + odd) * 64)     = make_uint2(h0, h1);
    *(uint2*)(sb + (j * 4 + 2 + odd) * 64) = make_uint2(l0, l1);
}

__device__ __forceinline__ void sb_load(const uint32_t* sb, int kt,
                                        uint32_t (&h)[4], uint32_t (&l)[4])
{
    uint2 a = *(const uint2*)(sb + (kt * 4 + 0) * 64);
    uint2 b = *(const uint2*)(sb + (kt * 4 + 1) * 64);
    uint2 c = *(const uint2*)(sb + (kt * 4 + 2) * 64);
    uint2 d = *(const uint2*)(sb + (kt * 4 + 3) * 64);
    h[0] = a.x; h[1] = a.y; h[2] = b.x; h[3] = b.y;
    l[0] = c.x; l[1] = c.y; l[2] = d.x; l[3] = d.y;
}

// ---------------- weight packing kernel (once per launch) ----------------
__global__ void pack_kernel(Params p)
{
    int tid = blockIdx.x * blockDim.x + threadIdx.x;
    if (tid >= 16384) return;
    int bid = tid >> 5, lane = tid & 31;
    int l = 0;
    while (bid >= c_bcum[l + 1]) l++;
    int NT = c_NT[l];
    int N  = NT * 8;
    int b  = bid - c_bcum[l];
    int kt = b / NT, nt = b % NT;
    int g = lane >> 2, t = lane & 3;
    const float* W;
    switch (l) {
        case 0: W = p.hW1; break;  case 1: W = p.hW2; break;  case 2: W = p.hW3; break;
        case 3: W = p.bW1; break;  case 4: W = p.bW2; break;  case 5: W = p.bW3; break;
        case 6: W = p.cW1; break;  case 7: W = p.cW2; break;  default: W = p.cW3; break;
    }
    int k0 = kt * 16, n = nt * 8 + g;
    float w00 = W[(k0 + 2*t)     * N + n];
    float w01 = W[(k0 + 2*t + 1) * N + n];
    float w10 = W[(k0 + 8 + 2*t)     * N + n];
    float w11 = W[(k0 + 8 + 2*t + 1) * N + n];
    uint4 v;
    split2(w00, w01, v.x, v.z);
    split2(w10, w11, v.y, v.w);
    g_wpk[c_u4off[l] + b * 32 + lane] = v;
}

// ---------------- layer variants ----------------

// reg in -> reg out (same frag array, in-place safe)
template <int KT, int NT, int IKT>
__device__ __forceinline__ void layer_rr(const uint4* __restrict__ Wp,
                                         const float* __restrict__ bg,
                                         uint32_t (&ah)[IKT][4], uint32_t (&al)[IKT][4],
                                         int lane, int t)
{
    float acc[NT][4];
#pragma unroll
    for (int nt = 0; nt < NT; nt++) {
        acc[nt][0] = 0.f; acc[nt][1] = 0.f; acc[nt][2] = 0.f; acc[nt][3] = 0.f;
    }
    const uint4* wl = Wp + lane;
#pragma unroll
    for (int kt = 0; kt < KT; kt++) {
#pragma unroll
        for (int nt = 0; nt < NT; nt++) {
            uint4 w = __ldg(wl + (kt * NT + nt) * 32);
            mma16(acc[nt], ah[kt][0], ah[kt][1], ah[kt][2], ah[kt][3], w.x, w.y);
            mma16(acc[nt], al[kt][0], al[kt][1], al[kt][2], al[kt][3], w.x, w.y);
            mma16(acc[nt], ah[kt][0], ah[kt][1], ah[kt][2], ah[kt][3], w.z, w.w);
        }
    }
#pragma unroll
    for (int nt = 0; nt < NT; nt++) {
        float2 bb = __ldg((const float2*)(bg + nt * 8 + 2 * t));
        float v0 = leaky(acc[nt][0] + bb.x);
        float v1 = leaky(acc[nt][1] + bb.y);
        float v2 = leaky(acc[nt][2] + bb.x);
        float v3 = leaky(acc[nt][3] + bb.y);
        const int j = nt >> 1, h = (nt & 1) * 2;
        split2(v0, v1, ah[j][h],     al[j][h]);
        split2(v2, v3, ah[j][h + 1], al[j][h + 1]);
    }
}

// reg in -> smem out at kt slots OFF.. (no activation: used for hb3/bb3)
template <int KT, int NT, int IKT, int OFF>
__device__ __forceinline__ void layer_rs(const uint4* __restrict__ Wp,
                                         const float* __restrict__ bg,
                                         uint32_t (&ah)[IKT][4], uint32_t (&al)[IKT][4],
                                         uint32_t* sb, int lane, int t)
{
    float acc[NT][4];
#pragma unroll
    for (int nt = 0; nt < NT; nt++) {
        acc[nt][0] = 0.f; acc[nt][1] = 0.f; acc[nt][2] = 0.f; acc[nt][3] = 0.f;
    }
    const uint4* wl = Wp + lane;
#pragma unroll
    for (int kt = 0; kt < KT; kt++) {
#pragma unroll
        for (int nt = 0; nt < NT; nt++) {
            uint4 w = __ldg(wl + (kt * NT + nt) * 32);
            mma16(acc[nt], ah[kt][0], ah[kt][1], ah[kt][2], ah[kt][3], w.x, w.y);
            mma16(acc[nt], al[kt][0], al[kt][1], al[kt][2], al[kt][3], w.x, w.y);
            mma16(acc[nt], ah[kt][0], ah[kt][1], ah[kt][2], ah[kt][3], w.z, w.w);
        }
    }
#pragma unroll
    for (int nt = 0; nt < NT; nt++) {
        float2 bb = __ldg((const float2*)(bg + nt * 8 + 2 * t));
        sb_emit(sb, OFF + (nt >> 1), nt & 1,
                acc[nt][0] + bb.x, acc[nt][1] + bb.y,
                acc[nt][2] + bb.x, acc[nt][3] + bb.y);
    }
}

// smem in -> smem out, in-place over full ring (reads all kt before emission)
template <int KT, int NT>
__device__ __forceinline__ void layer_ss(const uint4* __restrict__ Wp,
                                         const float* __restrict__ bg,
                                         uint32_t* sb, int lane, int t)
{
    float acc[NT][4];
#pragma unroll
    for (int nt = 0; nt < NT; nt++) {
        acc[nt][0] = 0.f; acc[nt][1] = 0.f; acc[nt][2] = 0.f; acc[nt][3] = 0.f;
    }
    const uint4* wl = Wp + lane;
#pragma unroll
    for (int kt = 0; kt < KT; kt++) {
        uint32_t h[4], l[4];
        sb_load(sb, kt, h, l);
#pragma unroll
        for (int nt = 0; nt < NT; nt++) {
            uint4 w = __ldg(wl + (kt * NT + nt) * 32);
            mma16(acc[nt], h[0], h[1], h[2], h[3], w.x, w.y);
            mma16(acc[nt], l[0], l[1], l[2], l[3], w.x, w.y);
            mma16(acc[nt], h[0], h[1], h[2], h[3], w.z, w.w);
        }
    }
#pragma unroll
    for (int nt = 0; nt < NT; nt++) {
        float2 bb = __ldg((const float2*)(bg + nt * 8 + 2 * t));
        sb_emit(sb, nt >> 1, nt & 1,
                leaky(acc[nt][0] + bb.x), leaky(acc[nt][1] + bb.y),
                leaky(acc[nt][2] + bb.x), leaky(acc[nt][3] + bb.y));
    }
}

// smem in -> reg out
template <int KT, int NT, int OKT>
__device__ __forceinline__ void layer_sr(const uint4* __restrict__ Wp,
                                         const float* __restrict__ bg,
                                         const uint32_t* sb,
                                         uint32_t (&oh)[OKT][4], uint32_t (&ol)[OKT][4],
                                         int lane, int t)
{
    float acc[NT][4];
#pragma unroll
    for (int nt = 0; nt < NT; nt++) {
        acc[nt][0] = 0.f; acc[nt][1] = 0.f; acc[nt][2] = 0.f; acc[nt][3] = 0.f;
    }
    const uint4* wl = Wp + lane;
#pragma unroll
    for (int kt = 0; kt < KT; kt++) {
        uint32_t h[4], l[4];
        sb_load(sb, kt, h, l);
#pragma unroll
        for (int nt = 0; nt < NT; nt++) {
            uint4 w = __ldg(wl + (kt * NT + nt) * 32);
            mma16(acc[nt], h[0], h[1], h[2], h[3], w.x, w.y);
            mma16(acc[nt], l[0], l[1], l[2], l[3], w.x, w.y);
            mma16(acc[nt], h[0], h[1], h[2], h[3], w.z, w.w);
        }
    }
#pragma unroll
    for (int nt = 0; nt < NT; nt++) {
        float2 bb = __ldg((const float2*)(bg + nt * 8 + 2 * t));
        float v0 = leaky(acc[nt][0] + bb.x);
        float v1 = leaky(acc[nt][1] + bb.y);
        float v2 = leaky(acc[nt][2] + bb.x);
        float v3 = leaky(acc[nt][3] + bb.y);
        const int j = nt >> 1, h = (nt & 1) * 2;
        split2(v0, v1, oh[j][h],     ol[j][h]);
        split2(v2, v3, oh[j][h + 1], ol[j][h + 1]);
    }
}

// final layer: raw f32 accumulators
template <int KT, int IKT>
__device__ __forceinline__ void layer_last(const uint4* __restrict__ Wp,
                                           uint32_t (&ah)[IKT][4], uint32_t (&al)[IKT][4],
                                           float (&acc)[8][4], int lane)
{
#pragma unroll
    for (int nt = 0; nt < 8; nt++) {
        acc[nt][0] = 0.f; acc[nt][1] = 0.f; acc[nt][2] = 0.f; acc[nt][3] = 0.f;
    }
    const uint4* wl = Wp + lane;
#pragma unroll
    for (int kt = 0; kt < KT; kt++) {
#pragma unroll
        for (int nt = 0; nt < 8; nt++) {
            uint4 w = __ldg(wl + (kt * 8 + nt) * 32);
            mma16(acc[nt], ah[kt][0], ah[kt][1], ah[kt][2], ah[kt][3], w.x, w.y);
            mma16(acc[nt], al[kt][0], al[kt][1], al[kt][2], al[kt][3], w.x, w.y);
            mma16(acc[nt], ah[kt][0], ah[kt][1], ah[kt][2], ah[kt][3], w.z, w.w);
        }
    }
}

__global__ void __launch_bounds__(NTHREADS, 4)
preproc_kernel(Params p)
{
    __shared__ uint32_t SB[NWARPS * SB_WARP_WORDS];   // 36.9 KB

    const int warp = threadIdx.x >> 5;
    const int lane = threadIdx.x & 31;
    const int g = lane >> 2, t = lane & 3;
    const int row0 = blockIdx.x * TM + warp * 16;

    uint32_t* sb = SB + warp * SB_WARP_WORDS + lane * 2;   // per-lane private

    const int rg  = min(row0 + g,     p.nrows - 1);
    const int rg8 = min(row0 + g + 8, p.nrows - 1);
    const float* st0 = p.state + (size_t)rg  * 50;
    const float* st1 = p.state + (size_t)rg8 * 50;

    // ---------- hand: gather frags + 64->64->64->64 -> SB kt 0..3 ----------
    {
        uint32_t G[4][4], Gl[4][4];
#pragma unroll
        for (int c = 0; c < 4; c++) {
            int s0 = (int)__ldg(st0 + 2 * c + 1), r0i = (int)__ldg(st0 + 2 * c);
            int s1 = (int)__ldg(st1 + 2 * c + 1), r1i = (int)__ldg(st1 + 2 * c);
            float2 e;
            e = __ldg((const float2*)(p.suit + s0  * 8 + 2 * t)); split2(e.x, e.y, G[c][0], Gl[c][0]);
            e = __ldg((const float2*)(p.suit + s1  * 8 + 2 * t)); split2(e.x, e.y, G[c][1], Gl[c][1]);
            e = __ldg((const float2*)(p.rank + r0i * 8 + 2 * t)); split2(e.x, e.y, G[c][2], Gl[c][2]);
            e = __ldg((const float2*)(p.rank + r1i * 8 + 2 * t)); split2(e.x, e.y, G[c][3], Gl[c][3]);
        }
        layer_rr<4, 8, 4>(g_wpk + 0,    p.hb1, G, Gl, lane, t);
        layer_rr<4, 8, 4>(g_wpk + 1024, p.hb2, G, Gl, lane, t);
        layer_rs<4, 8, 4, 0>(g_wpk + 2048, p.hb3, G, Gl, sb, lane, t);
    }

    // ---------- board: gather frags + 80->80->80->80 -> SB kt 4..8 ----------
    {
        uint32_t Bd[5][4], Bl[5][4];
#pragma unroll
        for (int c = 0; c < 5; c++) {
            int s0 = (int)__ldg(st0 + 9 + 2 * c), r0i = (int)__ldg(st0 + 8 + 2 * c);
            int s1 = (int)__ldg(st1 + 9 + 2 * c), r1i = (int)__ldg(st1 + 8 + 2 * c);
            float2 e;
            e = __ldg((const float2*)(p.suit + s0  * 8 + 2 * t)); split2(e.x, e.y, Bd[c][0], Bl[c][0]);
            e = __ldg((const float2*)(p.suit + s1  * 8 + 2 * t)); split2(e.x, e.y, Bd[c][1], Bl[c][1]);
            e = __ldg((const float2*)(p.rank + r0i * 8 + 2 * t)); split2(e.x, e.y, Bd[c][2], Bl[c][2]);
            e = __ldg((const float2*)(p.rank + r1i * 8 + 2 * t)); split2(e.x, e.y, Bd[c][3], Bl[c][3]);
        }
        layer_rr<5, 10, 5>(g_wpk + 3072, p.bb1, Bd, Bl, lane, t);
        layer_rr<5, 10, 5>(g_wpk + 4672, p.bb2, Bd, Bl, lane, t);
        layer_rs<5, 10, 5, 4>(g_wpk + 6272, p.bb3, Bd, Bl, sb, lane, t);
    }

    // ---------- hb chain: 144->144 (smem->smem), 144->64 (smem->reg), 64->64 ----------
    layer_ss<9, 18>(g_wpk + 7872, p.cb1, sb, lane, t);
    uint32_t D[4][4], Dl[4][4];
    layer_sr<9, 8, 4>(g_wpk + 13056, p.cb2, sb, D, Dl, lane, t);
    float accF[8][4];
    layer_last<4, 4>(g_wpk + 15360, D, Dl, accF, lane);

    // ---------- store hb result (cols 0..63) ----------
    {
        float2 bb[8];
#pragma unroll
        for (int nt = 0; nt < 8; nt++)
            bb[nt] = __ldg((const float2*)(p.cb3 + nt * 8 + 2 * t));
        if (row0 + g < p.nrows) {
            float* o = p.out + (size_t)(row0 + g) * 312;
#pragma unroll
            for (int nt = 0; nt < 8; nt++)
                *(float2*)(o + nt * 8 + 2 * t) =
                    make_float2(accF[nt][0] + bb[nt].x, accF[nt][1] + bb[nt].y);
        }
        if (row0 + g + 8 < p.nrows) {
            float* o = p.out + (size_t)(row0 + g + 8) * 312;
#pragma unroll
            for (int nt = 0; nt < 8; nt++)
                *(float2*)(o + nt * 8 + 2 * t) =
                    make_float2(accF[nt][2] + bb[nt].x, accF[nt][3] + bb[nt].y);
        }
    }

    // ---------- aux epilogue: cols 64..311 from state ----------
    const float* tabs[6] = { p.pos, p.action, p.active, p.street, p.nump, p.blind };
#pragma unroll 1
    for (int r = 0; r < 16; r++) {
        int row = row0 + r;
        if (row >= p.nrows) continue;
        float* orow = p.out + (size_t)row * 312;
        const float* st = p.state + (size_t)row * 50;
        for (int tt = lane; tt < 248; tt += 32) {
            int s = tt >> 3, d = tt & 7;
            int kind = c_kind[s], col = c_col[s];
            float v;
            if (kind == 6) {
                float sc = st[c_scol[col]];
                int w = c_widx[col];
                v = fmaf(sc, __ldg(p.sW + w * 8 + d), __ldg(p.sb + w * 8 + d));
            } else {
                int iv = (int)st[col];
                v = __ldg(tabs[kind] + iv * 8 + d);
            }
            orow[64 + tt] = v;
        }
    }
}

extern "C" void kernel_launch(void* const* d_in, const int* in_sizes, int n_in,
                              void* d_out, int out_size)
{
    Params p;
    p.state  = (const float*)d_in[0];
    p.suit   = (const float*)d_in[1];
    p.rank   = (const float*)d_in[2];
    p.hW1 = (const float*)d_in[3];  p.hb1 = (const float*)d_in[4];
    p.hW2 = (const float*)d_in[5];  p.hb2 = (const float*)d_in[6];
    p.hW3 = (const float*)d_in[7];  p.hb3 = (const float*)d_in[8];
    p.bW1 = (const float*)d_in[9];  p.bb1 = (const float*)d_in[10];
    p.bW2 = (const float*)d_in[11]; p.bb2 = (const float*)d_in[12];
    p.bW3 = (const float*)d_in[13]; p.bb3 = (const float*)d_in[14];
    p.cW1 = (const float*)d_in[15]; p.cb1 = (const float*)d_in[16];
    p.cW2 = (const float*)d_in[17]; p.cb2 = (const float*)d_in[18];
    p.cW3 = (const float*)d_in[19]; p.cb3 = (const float*)d_in[20];
    p.pos    = (const float*)d_in[21];
    p.action = (const float*)d_in[22];
    p.active = (const float*)d_in[23];
    p.street = (const float*)d_in[24];
    p.nump   = (const float*)d_in[25];
    p.blind  = (const float*)d_in[26];
    p.sW     = (const float*)d_in[27];
    p.sb     = (const float*)d_in[28];
    p.out    = (float*)d_out;
    p.nrows  = out_size / 312;

    pack_kernel<<<64, 256>>>(p);

    int grid = (p.nrows + TM - 1) / TM;
    preproc_kernel<<<grid, NTHREADS>>>(p);
}

// round 13
// speedup vs baseline: 1.6472x; 1.6472x over previous
#include <cuda_runtime.h>
#include <cuda_fp16.h>
#include <cstdint>

#define NWARPS    4
#define NTHREADS  (NWARPS * 32)
#define TM        (NWARPS * 16)     // 64 rows per CTA

// Packed fp16 B-fragments (hi only, 2-term scheme), nt-paired:
// per (layer, kt16, ntpair, lane): uint4 =
// {bh0(nt0), bh1(nt0), bh0(nt1), bh1(nt1)} where bh0 covers k=2t,2t+1 and
// bh1 covers k=2t+8,2t+9, col n = nt*8 + g.  8192 uint4 = 128 KB (L1-resident).
__device__ uint4 g_wpk[8192];

// layer tables (pack kernel): NP = N/16 pairs, pair-block cumsum, uint4 offset
__constant__ int c_NP[9]   = {4,4,4,5,5,5,9,4,4};
__constant__ int c_bcum[10]= {0,16,32,48,73,98,123,204,240,256};
__constant__ int c_u4off[9]= {0,512,1024,1536,2336,3136,3936,6528,7680};

// Epilogue segment descriptors (31 segments of 8 after the 64 hb outputs)
__constant__ int c_kind[31] = {3,0,2,2,2,2,2,0,0,0,0,0,6,6,6,6,0,1,5,6,1,0,5,4,0,6,6,6,6,6,6};
__constant__ int c_col[31]  = {18,20,22,23,24,25,26,27,28,29,30,31,0,1,2,3,35,36,37,4,32,33,34,19,38,5,6,7,8,9,10};
__constant__ int c_scol[11] = {40,41,42,43,39,44,45,46,47,48,49};
__constant__ int c_widx[11] = {0,2,3,5,1,4,4,4,4,4,4};

struct Params {
    const float *state;
    const float *suit, *rank;
    const float *hW1,*hb1,*hW2,*hb2,*hW3,*hb3;
    const float *bW1,*bb1,*bW2,*bb2,*bW3,*bb3;
    const float *cW1,*cb1,*cW2,*cb2,*cW3,*cb3;
    const float *pos,*action,*active,*street,*nump,*blind;
    const float *sW,*sb;
    float *out;
    int nrows;
};

__device__ __forceinline__ float leaky(float v) { return v > 0.0f ? v : 0.01f * v; }

__device__ __forceinline__ uint32_t h2bits(__half2 h) {
    return *reinterpret_cast<uint32_t*>(&h);
}

// split (x,y) into packed fp16 hi and lo half2 bit patterns (A side stays near-exact:
// (Ah+Al) represents A to ~2^-22, and both multiply the same Bh)
__device__ __forceinline__ void split2(float x, float y, uint32_t& hi, uint32_t& lo) {
    __half2 h = __floats2half2_rn(x, y);
    float2 hf = __half22float2(h);
    __half2 l = __floats2half2_rn(x - hf.x, y - hf.y);
    hi = h2bits(h);
    lo = h2bits(l);
}

__device__ __forceinline__ void mma16(float (&c)[4],
                                      uint32_t a0, uint32_t a1, uint32_t a2, uint32_t a3,
                                      uint32_t b0, uint32_t b1)
{
    asm volatile("mma.sync.aligned.m16n8k16.row.col.f32.f16.f16.f32 "
                 "{%0,%1,%2,%3}, {%4,%5,%6,%7}, {%8,%9}, {%0,%1,%2,%3};\n"
                 : "+f"(c[0]), "+f"(c[1]), "+f"(c[2]), "+f"(c[3])
                 : "r"(a0), "r"(a1), "r"(a2), "r"(a3), "r"(b0), "r"(b1));
}

// ---------------- weight packing kernel (once per launch) ----------------
__global__ void pack_kernel(Params p)
{
    int tid = blockIdx.x * blockDim.x + threadIdx.x;
    if (tid >= 8192) return;
    int bid = tid >> 5, lane = tid & 31;
    int l = 0;
    while (bid >= c_bcum[l + 1]) l++;
    int NP = c_NP[l];
    int N  = NP * 16;
    int b  = bid - c_bcum[l];
    int kt = b / NP, pr = b % NP;
    int g = lane >> 2, t = lane & 3;
    const float* W;
    switch (l) {
        case 0: W = p.hW1; break;  case 1: W = p.hW2; break;  case 2: W = p.hW3; break;
        case 3: W = p.bW1; break;  case 4: W = p.bW2; break;  case 5: W = p.bW3; break;
        case 6: W = p.cW1; break;  case 7: W = p.cW2; break;  default: W = p.cW3; break;
    }
    int k0 = kt * 16;
    int n0 = pr * 16 + g;      // col of nt0 = 2*pr
    int n1 = n0 + 8;           // col of nt1 = 2*pr+1
    uint4 v;
    v.x = h2bits(__floats2half2_rn(W[(k0 + 2*t) * N + n0], W[(k0 + 2*t + 1) * N + n0]));
    v.y = h2bits(__floats2half2_rn(W[(k0 + 8 + 2*t) * N + n0], W[(k0 + 8 + 2*t + 1) * N + n0]));
    v.z = h2bits(__floats2half2_rn(W[(k0 + 2*t) * N + n1], W[(k0 + 2*t + 1) * N + n1]));
    v.w = h2bits(__floats2half2_rn(W[(k0 + 8 + 2*t) * N + n1], W[(k0 + 8 + 2*t + 1) * N + n1]));
    g_wpk[c_u4off[l] + b * 32 + lane] = v;
}

// ---------------- register-chained dense layer (2-term: A·Bh) ----------------
// Consumes A-frags ah/al (fp16 hi/lo, kt-tiles 0..KT-1), emits the NEXT layer's
// A-frags into oh/ol at kt slots OFF..OFF+NT/2-1. May alias (reads precede writes).
template <int KT, int NT, bool ACT, int IKT, int OKT, int OFF>
__device__ __forceinline__ void layer_mid(const uint4* __restrict__ Wp,
                                          const float* __restrict__ bg,
                                          uint32_t (&ah)[IKT][4], uint32_t (&al)[IKT][4],
                                          uint32_t (&oh)[OKT][4], uint32_t (&ol)[OKT][4],
                                          int lane, int t)
{
    constexpr int NP = NT / 2;
    float acc[NT][4];
#pragma unroll
    for (int nt = 0; nt < NT; nt++) {
        acc[nt][0] = 0.f; acc[nt][1] = 0.f; acc[nt][2] = 0.f; acc[nt][3] = 0.f;
    }
    const uint4* wl = Wp + lane;
#pragma unroll
    for (int kt = 0; kt < KT; kt++) {
#pragma unroll
        for (int pp = 0; pp < NP; pp++) {
            uint4 w = __ldg(wl + (kt * NP + pp) * 32);
            mma16(acc[2*pp],   ah[kt][0], ah[kt][1], ah[kt][2], ah[kt][3], w.x, w.y);
            mma16(acc[2*pp],   al[kt][0], al[kt][1], al[kt][2], al[kt][3], w.x, w.y);
            mma16(acc[2*pp+1], ah[kt][0], ah[kt][1], ah[kt][2], ah[kt][3], w.z, w.w);
            mma16(acc[2*pp+1], al[kt][0], al[kt][1], al[kt][2], al[kt][3], w.z, w.w);
        }
    }
#pragma unroll
    for (int nt = 0; nt < NT; nt++) {
        float2 bb = __ldg((const float2*)(bg + nt * 8 + 2 * t));
        float v0 = acc[nt][0] + bb.x;
        float v1 = acc[nt][1] + bb.y;
        float v2 = acc[nt][2] + bb.x;
        float v3 = acc[nt][3] + bb.y;
        if (ACT) { v0 = leaky(v0); v1 = leaky(v1); v2 = leaky(v2); v3 = leaky(v3); }
        const int j = OFF + (nt >> 1);
        const int h = (nt & 1) * 2;
        split2(v0, v1, oh[j][h],     ol[j][h]);
        split2(v2, v3, oh[j][h + 1], ol[j][h + 1]);
    }
}

// Final layer: emit raw f32 accumulators (bias added by caller at store time).
template <int KT, int IKT>
__device__ __forceinline__ void layer_last(const uint4* __restrict__ Wp,
                                           uint32_t (&ah)[IKT][4], uint32_t (&al)[IKT][4],
                                           float (&acc)[8][4], int lane)
{
#pragma unroll
    for (int nt = 0; nt < 8; nt++) {
        acc[nt][0] = 0.f; acc[nt][1] = 0.f; acc[nt][2] = 0.f; acc[nt][3] = 0.f;
    }
    const uint4* wl = Wp + lane;
#pragma unroll
    for (int kt = 0; kt < KT; kt++) {
#pragma unroll
        for (int pp = 0; pp < 4; pp++) {
            uint4 w = __ldg(wl + (kt * 4 + pp) * 32);
            mma16(acc[2*pp],   ah[kt][0], ah[kt][1], ah[kt][2], ah[kt][3], w.x, w.y);
            mma16(acc[2*pp],   al[kt][0], al[kt][1], al[kt][2], al[kt][3], w.x, w.y);
            mma16(acc[2*pp+1], ah[kt][0], ah[kt][1], ah[kt][2], ah[kt][3], w.z, w.w);
            mma16(acc[2*pp+1], al[kt][0], al[kt][1], al[kt][2], al[kt][3], w.z, w.w);
        }
    }
}

__global__ void __launch_bounds__(NTHREADS, 3)
preproc_kernel(Params p)
{
    const int warp = threadIdx.x >> 5;
    const int lane = threadIdx.x & 31;
    const int g = lane >> 2, t = lane & 3;
    const int row0 = blockIdx.x * TM + warp * 16;

    const int rg  = min(row0 + g,     p.nrows - 1);
    const int rg8 = min(row0 + g + 8, p.nrows - 1);
    const float* st0 = p.state + (size_t)rg  * 50;
    const float* st1 = p.state + (size_t)rg8 * 50;

    uint32_t CH[9][4], CL[9][4];     // concat / hb-chain frags (144 cols = 9 kt)

    // ---------- hand: gather frags + 64->64->64->64 chain -> CH[0..3] ----------
    {
        uint32_t G[4][4], Gl[4][4];
#pragma unroll
        for (int c = 0; c < 4; c++) {
            int s0 = (int)__ldg(st0 + 2 * c + 1), r0i = (int)__ldg(st0 + 2 * c);
            int s1 = (int)__ldg(st1 + 2 * c + 1), r1i = (int)__ldg(st1 + 2 * c);
            float2 e;
            e = __ldg((const float2*)(p.suit + s0  * 8 + 2 * t)); split2(e.x, e.y, G[c][0], Gl[c][0]);
            e = __ldg((const float2*)(p.suit + s1  * 8 + 2 * t)); split2(e.x, e.y, G[c][1], Gl[c][1]);
            e = __ldg((const float2*)(p.rank + r0i * 8 + 2 * t)); split2(e.x, e.y, G[c][2], Gl[c][2]);
            e = __ldg((const float2*)(p.rank + r1i * 8 + 2 * t)); split2(e.x, e.y, G[c][3], Gl[c][3]);
        }
        layer_mid<4, 8, true , 4, 4, 0>(g_wpk + 0,    p.hb1, G, Gl, G, Gl, lane, t);
        layer_mid<4, 8, true , 4, 4, 0>(g_wpk + 512,  p.hb2, G, Gl, G, Gl, lane, t);
        layer_mid<4, 8, false, 4, 9, 0>(g_wpk + 1024, p.hb3, G, Gl, CH, CL, lane, t);
    }

    // ---------- board: gather frags + 80->80->80->80 chain -> CH[4..8] ----------
    {
        uint32_t Bd[5][4], Bl[5][4];
#pragma unroll
        for (int c = 0; c < 5; c++) {
            int s0 = (int)__ldg(st0 + 9 + 2 * c), r0i = (int)__ldg(st0 + 8 + 2 * c);
            int s1 = (int)__ldg(st1 + 9 + 2 * c), r1i = (int)__ldg(st1 + 8 + 2 * c);
            float2 e;
            e = __ldg((const float2*)(p.suit + s0  * 8 + 2 * t)); split2(e.x, e.y, Bd[c][0], Bl[c][0]);
            e = __ldg((const float2*)(p.suit + s1  * 8 + 2 * t)); split2(e.x, e.y, Bd[c][1], Bl[c][1]);
            e = __ldg((const float2*)(p.rank + r0i * 8 + 2 * t)); split2(e.x, e.y, Bd[c][2], Bl[c][2]);
            e = __ldg((const float2*)(p.rank + r1i * 8 + 2 * t)); split2(e.x, e.y, Bd[c][3], Bl[c][3]);
        }
        layer_mid<5, 10, true , 5, 5, 0>(g_wpk + 1536, p.bb1, Bd, Bl, Bd, Bl, lane, t);
        layer_mid<5, 10, true , 5, 5, 0>(g_wpk + 2336, p.bb2, Bd, Bl, Bd, Bl, lane, t);
        layer_mid<5, 10, false, 5, 9, 4>(g_wpk + 3136, p.bb3, Bd, Bl, CH, CL, lane, t);
    }

    // ---------- hb: 144->144->64->64 (all register-chained, in-place) ----------
    layer_mid<9, 18, true, 9, 9, 0>(g_wpk + 3936, p.cb1, CH, CL, CH, CL, lane, t);
    layer_mid<9,  8, true, 9, 9, 0>(g_wpk + 6528, p.cb2, CH, CL, CH, CL, lane, t);
    float accF[8][4];
    layer_last<4, 9>(g_wpk + 7680, CH, CL, accF, lane);

    // ---------- store hb result (cols 0..63) ----------
    {
        float2 bb[8];
#pragma unroll
        for (int nt = 0; nt < 8; nt++)
            bb[nt] = __ldg((const float2*)(p.cb3 + nt * 8 + 2 * t));
        if (row0 + g < p.nrows) {
            float* o = p.out + (size_t)(row0 + g) * 312;
#pragma unroll
            for (int nt = 0; nt < 8; nt++)
                *(float2*)(o + nt * 8 + 2 * t) =
                    make_float2(accF[nt][0] + bb[nt].x, accF[nt][1] + bb[nt].y);
        }
        if (row0 + g + 8 < p.nrows) {
            float* o = p.out + (size_t)(row0 + g + 8) * 312;
#pragma unroll
            for (int nt = 0; nt < 8; nt++)
                *(float2*)(o + nt * 8 + 2 * t) =
                    make_float2(accF[nt][2] + bb[nt].x, accF[nt][3] + bb[nt].y);
        }
    }

    // ---------- aux epilogue: cols 64..311 from state ----------
    const float* tabs[6] = { p.pos, p.action, p.active, p.street, p.nump, p.blind };
#pragma unroll 1
    for (int r = 0; r < 16; r++) {
        int row = row0 + r;
        if (row >= p.nrows) continue;
        float* orow = p.out + (size_t)row * 312;
        const float* st = p.state + (size_t)row * 50;
        for (int tt = lane; tt < 248; tt += 32) {
            int s = tt >> 3, d = tt & 7;
            int kind = c_kind[s], col = c_col[s];
            float v;
            if (kind == 6) {
                float sc = st[c_scol[col]];
                int w = c_widx[col];
                v = fmaf(sc, __ldg(p.sW + w * 8 + d), __ldg(p.sb + w * 8 + d));
            } else {
                int iv = (int)st[col];
                v = __ldg(tabs[kind] + iv * 8 + d);
            }
            orow[64 + tt] = v;
        }
    }
}

extern "C" void kernel_launch(void* const* d_in, const int* in_sizes, int n_in,
                              void* d_out, int out_size)
{
    Params p;
    p.state  = (const float*)d_in[0];
    p.suit   = (const float*)d_in[1];
    p.rank   = (const float*)d_in[2];
    p.hW1 = (const float*)d_in[3];  p.hb1 = (const float*)d_in[4];
    p.hW2 = (const float*)d_in[5];  p.hb2 = (const float*)d_in[6];
    p.hW3 = (const float*)d_in[7];  p.hb3 = (const float*)d_in[8];
    p.bW1 = (const float*)d_in[9];  p.bb1 = (const float*)d_in[10];
    p.bW2 = (const float*)d_in[11]; p.bb2 = (const float*)d_in[12];
    p.bW3 = (const float*)d_in[13]; p.bb3 = (const float*)d_in[14];
    p.cW1 = (const float*)d_in[15]; p.cb1 = (const float*)d_in[16];
    p.cW2 = (const float*)d_in[17]; p.cb2 = (const float*)d_in[18];
    p.cW3 = (const float*)d_in[19]; p.cb3 = (const float*)d_in[20];
    p.pos    = (const float*)d_in[21];
    p.action = (const float*)d_in[22];
    p.active = (const float*)d_in[23];
    p.street = (const float*)d_in[24];
    p.nump   = (const float*)d_in[25];
    p.blind  = (const float*)d_in[26];
    p.sW     = (const float*)d_in[27];
    p.sb     = (const float*)d_in[28];
    p.out    = (float*)d_out;
    p.nrows  = out_size / 312;

    pack_kernel<<<32, 256>>>(p);

    int grid = (p.nrows + TM - 1) / TM;
    preproc_kernel<<<grid, NTHREADS>>>(p);
}

// round 16
// speedup vs baseline: 1.9727x; 1.1976x over previous
#include <cuda_runtime.h>
#include <cuda_fp16.h>
#include <cstdint>

#define NWARPS    4
#define NTHREADS  (NWARPS * 32)
#define TM        (NWARPS * 16)     // 64 rows per CTA

// Packed fp16 B-fragments (hi only), nt-paired:
// per (layer, kt16, ntpair, lane): uint4 =
// {bh0(nt0), bh1(nt0), bh0(nt1), bh1(nt1)} where bh0 covers k=2t,2t+1 and
// bh1 covers k=2t+8,2t+9, col n = nt*8 + g.  8192 uint4 = 128 KB (L1-resident).
__device__ uint4 g_wpk[8192];

// layer tables (pack kernel): NP = N/16 pairs, pair-block cumsum, uint4 offset
__constant__ int c_NP[9]   = {4,4,4,5,5,5,9,4,4};
__constant__ int c_bcum[10]= {0,16,32,48,73,98,123,204,240,256};
__constant__ int c_u4off[9]= {0,512,1024,1536,2336,3136,3936,6528,7680};

// Epilogue segment descriptors (31 segments of 8 after the 64 hb outputs)
__constant__ int c_kind[31] = {3,0,2,2,2,2,2,0,0,0,0,0,6,6,6,6,0,1,5,6,1,0,5,4,0,6,6,6,6,6,6};
__constant__ int c_col[31]  = {18,20,22,23,24,25,26,27,28,29,30,31,0,1,2,3,35,36,37,4,32,33,34,19,38,5,6,7,8,9,10};
__constant__ int c_scol[11] = {40,41,42,43,39,44,45,46,47,48,49};
__constant__ int c_widx[11] = {0,2,3,5,1,4,4,4,4,4,4};

struct Params {
    const float *state;
    const float *suit, *rank;
    const float *hW1,*hb1,*hW2,*hb2,*hW3,*hb3;
    const float *bW1,*bb1,*bW2,*bb2,*bW3,*bb3;
    const float *cW1,*cb1,*cW2,*cb2,*cW3,*cb3;
    const float *pos,*action,*active,*street,*nump,*blind;
    const float *sW,*sb;
    float *out;
    int nrows;
};

__device__ __forceinline__ float leaky(float v) { return v > 0.0f ? v : 0.01f * v; }

__device__ __forceinline__ uint32_t h2bits(__half2 h) {
    return *reinterpret_cast<uint32_t*>(&h);
}
__device__ __forceinline__ uint32_t pack16(float x, float y) {
    return h2bits(__floats2half2_rn(x, y));
}

__device__ __forceinline__ void mma16(float (&c)[4],
                                      uint32_t a0, uint32_t a1, uint32_t a2, uint32_t a3,
                                      uint32_t b0, uint32_t b1)
{
    asm volatile("mma.sync.aligned.m16n8k16.row.col.f32.f16.f16.f32 "
                 "{%0,%1,%2,%3}, {%4,%5,%6,%7}, {%8,%9}, {%0,%1,%2,%3};\n"
                 : "+f"(c[0]), "+f"(c[1]), "+f"(c[2]), "+f"(c[3])
                 : "r"(a0), "r"(a1), "r"(a2), "r"(a3), "r"(b0), "r"(b1));
}

// ---------------- weight packing kernel (once per launch) ----------------
__global__ void pack_kernel(Params p)
{
    int tid = blockIdx.x * blockDim.x + threadIdx.x;
    if (tid >= 8192) return;
    int bid = tid >> 5, lane = tid & 31;
    int l = 0;
    while (bid >= c_bcum[l + 1]) l++;
    int NP = c_NP[l];
    int N  = NP * 16;
    int b  = bid - c_bcum[l];
    int kt = b / NP, pr = b % NP;
    int g = lane >> 2, t = lane & 3;
    const float* W;
    switch (l) {
        case 0: W = p.hW1; break;  case 1: W = p.hW2; break;  case 2: W = p.hW3; break;
        case 3: W = p.bW1; break;  case 4: W = p.bW2; break;  case 5: W = p.bW3; break;
        case 6: W = p.cW1; break;  case 7: W = p.cW2; break;  default: W = p.cW3; break;
    }
    int k0 = kt * 16;
    int n0 = pr * 16 + g;      // col of nt0 = 2*pr
    int n1 = n0 + 8;           // col of nt1 = 2*pr+1
    uint4 v;
    v.x = pack16(W[(k0 + 2*t) * N + n0],     W[(k0 + 2*t + 1) * N + n0]);
    v.y = pack16(W[(k0 + 8 + 2*t) * N + n0], W[(k0 + 8 + 2*t + 1) * N + n0]);
    v.z = pack16(W[(k0 + 2*t) * N + n1],     W[(k0 + 2*t + 1) * N + n1]);
    v.w = pack16(W[(k0 + 8 + 2*t) * N + n1], W[(k0 + 8 + 2*t + 1) * N + n1]);
    g_wpk[c_u4off[l] + b * 32 + lane] = v;
}

// ---------------- register-chained dense layer (single-term fp16) ----------------
// Consumes A-frags ah (fp16, kt-tiles 0..KT-1), emits the NEXT layer's A-frags
// into oh at kt slots OFF..OFF+NT/2-1. May alias (all reads precede writes).
template <int KT, int NT, bool ACT, int IKT, int OKT, int OFF>
__device__ __forceinline__ void layer_mid(const uint4* __restrict__ Wp,
                                          const float* __restrict__ bg,
                                          uint32_t (&ah)[IKT][4],
                                          uint32_t (&oh)[OKT][4],
                                          int lane, int t)
{
    constexpr int NP = NT / 2;
    float acc[NT][4];
#pragma unroll
    for (int nt = 0; nt < NT; nt++) {
        acc[nt][0] = 0.f; acc[nt][1] = 0.f; acc[nt][2] = 0.f; acc[nt][3] = 0.f;
    }
    const uint4* wl = Wp + lane;
#pragma unroll
    for (int kt = 0; kt < KT; kt++) {
#pragma unroll
        for (int pp = 0; pp < NP; pp++) {
            uint4 w = __ldg(wl + (kt * NP + pp) * 32);
            mma16(acc[2*pp],   ah[kt][0], ah[kt][1], ah[kt][2], ah[kt][3], w.x, w.y);
            mma16(acc[2*pp+1], ah[kt][0], ah[kt][1], ah[kt][2], ah[kt][3], w.z, w.w);
        }
    }
#pragma unroll
    for (int nt = 0; nt < NT; nt++) {
        float2 bb = __ldg((const float2*)(bg + nt * 8 + 2 * t));
        float v0 = acc[nt][0] + bb.x;
        float v1 = acc[nt][1] + bb.y;
        float v2 = acc[nt][2] + bb.x;
        float v3 = acc[nt][3] + bb.y;
        if (ACT) { v0 = leaky(v0); v1 = leaky(v1); v2 = leaky(v2); v3 = leaky(v3); }
        const int j = OFF + (nt >> 1);
        const int h = (nt & 1) * 2;
        oh[j][h]     = pack16(v0, v1);
        oh[j][h + 1] = pack16(v2, v3);
    }
}

// Final layer: emit raw f32 accumulators (bias added by caller at store time).
template <int KT, int IKT>
__device__ __forceinline__ void layer_last(const uint4* __restrict__ Wp,
                                           uint32_t (&ah)[IKT][4],
                                           float (&acc)[8][4], int lane)
{
#pragma unroll
    for (int nt = 0; nt < 8; nt++) {
        acc[nt][0] = 0.f; acc[nt][1] = 0.f; acc[nt][2] = 0.f; acc[nt][3] = 0.f;
    }
    const uint4* wl = Wp + lane;
#pragma unroll
    for (int kt = 0; kt < KT; kt++) {
#pragma unroll
        for (int pp = 0; pp < 4; pp++) {
            uint4 w = __ldg(wl + (kt * 4 + pp) * 32);
            mma16(acc[2*pp],   ah[kt][0], ah[kt][1], ah[kt][2], ah[kt][3], w.x, w.y);
            mma16(acc[2*pp+1], ah[kt][0], ah[kt][1], ah[kt][2], ah[kt][3], w.z, w.w);
        }
    }
}

__global__ void __launch_bounds__(NTHREADS, 4)
preproc_kernel(Params p)
{
    const int warp = threadIdx.x >> 5;
    const int lane = threadIdx.x & 31;
    const int g = lane >> 2, t = lane & 3;
    const int row0 = blockIdx.x * TM + warp * 16;

    const int rg  = min(row0 + g,     p.nrows - 1);
    const int rg8 = min(row0 + g + 8, p.nrows - 1);
    const float* st0 = p.state + (size_t)rg  * 50;
    const float* st1 = p.state + (size_t)rg8 * 50;

    uint32_t CH[9][4];     // concat / hb-chain frags (144 cols = 9 kt)

    // ---------- hand: gather frags + 64->64->64->64 chain -> CH[0..3] ----------
    {
        uint32_t G[4][4];
#pragma unroll
        for (int c = 0; c < 4; c++) {
            int s0 = (int)__ldg(st0 + 2 * c + 1), r0i = (int)__ldg(st0 + 2 * c);
            int s1 = (int)__ldg(st1 + 2 * c + 1), r1i = (int)__ldg(st1 + 2 * c);
            float2 e;
            e = __ldg((const float2*)(p.suit + s0  * 8 + 2 * t)); G[c][0] = pack16(e.x, e.y);
            e = __ldg((const float2*)(p.suit + s1  * 8 + 2 * t)); G[c][1] = pack16(e.x, e.y);
            e = __ldg((const float2*)(p.rank + r0i * 8 + 2 * t)); G[c][2] = pack16(e.x, e.y);
            e = __ldg((const float2*)(p.rank + r1i * 8 + 2 * t)); G[c][3] = pack16(e.x, e.y);
        }
        layer_mid<4, 8, true , 4, 4, 0>(g_wpk + 0,    p.hb1, G, G, lane, t);
        layer_mid<4, 8, true , 4, 4, 0>(g_wpk + 512,  p.hb2, G, G, lane, t);
        layer_mid<4, 8, false, 4, 9, 0>(g_wpk + 1024, p.hb3, G, CH, lane, t);
    }

    // ---------- board: gather frags + 80->80->80->80 chain -> CH[4..8] ----------
    {
        uint32_t Bd[5][4];
#pragma unroll
        for (int c = 0; c < 5; c++) {
            int s0 = (int)__ldg(st0 + 9 + 2 * c), r0i = (int)__ldg(st0 + 8 + 2 * c);
            int s1 = (int)__ldg(st1 + 9 + 2 * c), r1i = (int)__ldg(st1 + 8 + 2 * c);
            float2 e;
            e = __ldg((const float2*)(p.suit + s0  * 8 + 2 * t)); Bd[c][0] = pack16(e.x, e.y);
            e = __ldg((const float2*)(p.suit + s1  * 8 + 2 * t)); Bd[c][1] = pack16(e.x, e.y);
            e = __ldg((const float2*)(p.rank + r0i * 8 + 2 * t)); Bd[c][2] = pack16(e.x, e.y);
            e = __ldg((const float2*)(p.rank + r1i * 8 + 2 * t)); Bd[c][3] = pack16(e.x, e.y);
        }
        layer_mid<5, 10, true , 5, 5, 0>(g_wpk + 1536, p.bb1, Bd, Bd, lane, t);
        layer_mid<5, 10, true , 5, 5, 0>(g_wpk + 2336, p.bb2, Bd, Bd, lane, t);
        layer_mid<5, 10, false, 5, 9, 4>(g_wpk + 3136, p.bb3, Bd, CH, lane, t);
    }

    // ---------- hb: 144->144->64->64 (all register-chained, in-place) ----------
    layer_mid<9, 18, true, 9, 9, 0>(g_wpk + 3936, p.cb1, CH, CH, lane, t);
    layer_mid<9,  8, true, 9, 9, 0>(g_wpk + 6528, p.cb2, CH, CH, lane, t);
    float accF[8][4];
    layer_last<4, 9>(g_wpk + 7680, CH, accF, lane);

    // ---------- store hb result (cols 0..63) ----------
    {
        float2 bb[8];
#pragma unroll
        for (int nt = 0; nt < 8; nt++)
            bb[nt] = __ldg((const float2*)(p.cb3 + nt * 8 + 2 * t));
        if (row0 + g < p.nrows) {
            float* o = p.out + (size_t)(row0 + g) * 312;
#pragma unroll
            for (int nt = 0; nt < 8; nt++)
                *(float2*)(o + nt * 8 + 2 * t) =
                    make_float2(accF[nt][0] + bb[nt].x, accF[nt][1] + bb[nt].y);
        }
        if (row0 + g + 8 < p.nrows) {
            float* o = p.out + (size_t)(row0 + g + 8) * 312;
#pragma unroll
            for (int nt = 0; nt < 8; nt++)
                *(float2*)(o + nt * 8 + 2 * t) =
                    make_float2(accF[nt][2] + bb[nt].x, accF[nt][3] + bb[nt].y);
        }
    }

    // ---------- aux epilogue: cols 64..311, float2 per lane ----------
    const float* tabs[6] = { p.pos, p.action, p.active, p.street, p.nump, p.blind };
#pragma unroll 1
    for (int r = 0; r < 16; r++) {
        int row = row0 + r;
        if (row >= p.nrows) continue;
        float* orow = p.out + (size_t)row * 312;
        const float* st = p.state + (size_t)row * 50;
        // 124 float2 elements; pair (2q, 2q+1) never crosses a segment (segments are 8 wide)
        for (int q = lane; q < 124; q += 32) {
            int s = q >> 2;            // segment index
            int d = (q & 3) * 2;       // even sub-offset within segment
            int kind = c_kind[s], col = c_col[s];
            float2 v;
            if (kind == 6) {
                float sc = st[c_scol[col]];
                int w = c_widx[col];
                float2 w2 = __ldg((const float2*)(p.sW + w * 8 + d));
                float2 b2 = __ldg((const float2*)(p.sb + w * 8 + d));
                v = make_float2(fmaf(sc, w2.x, b2.x), fmaf(sc, w2.y, b2.y));
            } else {
                int iv = (int)st[col];
                v = __ldg((const float2*)(tabs[kind] + iv * 8 + d));
            }
            *(float2*)(orow + 64 + 2 * q) = v;
        }
    }
}

extern "C" void kernel_launch(void* const* d_in, const int* in_sizes, int n_in,
                              void* d_out, int out_size)
{
    Params p;
    p.state  = (const float*)d_in[0];
    p.suit   = (const float*)d_in[1];
    p.rank   = (const float*)d_in[2];
    p.hW1 = (const float*)d_in[3];  p.hb1 = (const float*)d_in[4];
    p.hW2 = (const float*)d_in[5];  p.hb2 = (const float*)d_in[6];
    p.hW3 = (const float*)d_in[7];  p.hb3 = (const float*)d_in[8];
    p.bW1 = (const float*)d_in[9];  p.bb1 = (const float*)d_in[10];
    p.bW2 = (const float*)d_in[11]; p.bb2 = (const float*)d_in[12];
    p.bW3 = (const float*)d_in[13]; p.bb3 = (const float*)d_in[14];
    p.cW1 = (const float*)d_in[15]; p.cb1 = (const float*)d_in[16];
    p.cW2 = (const float*)d_in[17]; p.cb2 = (const float*)d_in[18];
    p.cW3 = (const float*)d_in[19]; p.cb3 = (const float*)d_in[20];
    p.pos    = (const float*)d_in[21];
    p.action = (const float*)d_in[22];
    p.active = (const float*)d_in[23];
    p.street = (const float*)d_in[24];
    p.nump   = (const float*)d_in[25];
    p.blind  = (const float*)d_in[26];
    p.sW     = (const float*)d_in[27];
    p.sb     = (const float*)d_in[28];
    p.out    = (float*)d_out;
    p.nrows  = out_size / 312;

    pack_kernel<<<32, 256>>>(p);

    int grid = (p.nrows + TM - 1) / TM;
    preproc_kernel<<<grid, NTHREADS>>>(p);
}